// round 1
// baseline (speedup 1.0000x reference)
#include <cuda_runtime.h>
#include <math_constants.h>

#define BATCH  2
#define SEQ    4096
#define DMODEL 512
#define NH     8
#define DHEAD  64
#define SCALE  0.125f            // 64^-0.5
#define MTOT   (BATCH*SEQ)       // 8192

// ---- scratch (device globals; no allocations allowed) ----
__device__ __align__(16) float g_q[BATCH*NH*SEQ*DHEAD];   // [B,H,N,DH]
__device__ __align__(16) float g_k[BATCH*NH*SEQ*DHEAD];
__device__ __align__(16) float g_v[BATCH*NH*SEQ*DHEAD];
__device__ __align__(16) float g_o[MTOT*DMODEL];          // [B,N,H*DH] merged

// ============================================================
// Kernel 1: QKV projection. Y = X @ W, scatter to head layout.
// 64x64 tile per block, BK=32, 256 threads, 4x4 micro-tile.
// ============================================================
__global__ void __launch_bounds__(256) gemm_qkv(
    const float* __restrict__ X,
    const float* __restrict__ Wq,
    const float* __restrict__ Wk,
    const float* __restrict__ Wv)
{
    __shared__ float As[64][33];
    __shared__ float Bs[32][68];

    const float* W = (blockIdx.z == 0) ? Wq : (blockIdx.z == 1) ? Wk : Wv;
    float*       G = (blockIdx.z == 0) ? g_q : (blockIdx.z == 1) ? g_k : g_v;

    const int tid = threadIdx.x;
    const int tx = tid & 15, ty = tid >> 4;
    const int m0 = blockIdx.x * 64, n0 = blockIdx.y * 64;

    float acc[4][4] = {};

    for (int k0 = 0; k0 < DMODEL; k0 += 32) {
        // A tile: 64x32
        #pragma unroll
        for (int t = 0; t < 2; t++) {
            int id = tid + t * 256;
            int r = id >> 3, c = (id & 7) << 2;
            float4 v = *(const float4*)&X[(size_t)(m0 + r) * DMODEL + k0 + c];
            As[r][c + 0] = v.x; As[r][c + 1] = v.y;
            As[r][c + 2] = v.z; As[r][c + 3] = v.w;
        }
        // B tile: 32x64
        #pragma unroll
        for (int t = 0; t < 2; t++) {
            int id = tid + t * 256;
            int r = id >> 4, c = (id & 15) << 2;
            *(float4*)&Bs[r][c] =
                *(const float4*)&W[(size_t)(k0 + r) * DMODEL + n0 + c];
        }
        __syncthreads();

        #pragma unroll 8
        for (int kk = 0; kk < 32; kk++) {
            float a[4];
            #pragma unroll
            for (int i = 0; i < 4; i++) a[i] = As[ty * 4 + i][kk];
            float4 b = *(float4*)&Bs[kk][tx * 4];
            #pragma unroll
            for (int i = 0; i < 4; i++) {
                acc[i][0] += a[i] * b.x; acc[i][1] += a[i] * b.y;
                acc[i][2] += a[i] * b.z; acc[i][3] += a[i] * b.w;
            }
        }
        __syncthreads();
    }

    // scatter to [B,H,N,DH]
    const int nn = n0 + tx * 4;
    const int h = nn >> 6, dd = nn & 63;
    #pragma unroll
    for (int i = 0; i < 4; i++) {
        int m = m0 + ty * 4 + i;
        int b = m >> 12, ns = m & 4095;
        float4 v = make_float4(acc[i][0], acc[i][1], acc[i][2], acc[i][3]);
        *(float4*)&G[(((size_t)(b * NH + h) * SEQ + ns) * DHEAD) + dd] = v;
    }
}

// ============================================================
// Kernel 2: flash attention, fp32. One CTA = (b,h) x 64 query rows.
// Dynamic smem: Qs[64][68] + KPs[64][68] (K^T, then reused for P)
//               + Vs[64][68]  = 52224 bytes.
// ============================================================
__global__ void __launch_bounds__(256) attn_kernel()
{
    extern __shared__ float sm[];
    float (*Qs )[68] = (float(*)[68])(sm);
    float (*KPs)[68] = (float(*)[68])(sm + 64 * 68);
    float (*Vs )[68] = (float(*)[68])(sm + 2 * 64 * 68);

    const int tid = threadIdx.x;
    const int tx = tid & 15, ty = tid >> 4;
    const int bh = blockIdx.y;
    const int q0 = blockIdx.x * 64;

    const float* Qg = g_q + (size_t)bh * SEQ * DHEAD;
    const float* Kg = g_k + (size_t)bh * SEQ * DHEAD;
    const float* Vg = g_v + (size_t)bh * SEQ * DHEAD;

    // load Q tile (pre-scaled)
    #pragma unroll
    for (int t = 0; t < 4; t++) {
        int id = tid + t * 256;
        int r = id >> 4, c = (id & 15) << 2;
        float4 v = *(const float4*)&Qg[(size_t)(q0 + r) * DHEAD + c];
        v.x *= SCALE; v.y *= SCALE; v.z *= SCALE; v.w *= SCALE;
        *(float4*)&Qs[r][c] = v;
    }

    float m_i[4], l_i[4], o[4][4];
    #pragma unroll
    for (int i = 0; i < 4; i++) {
        m_i[i] = -CUDART_INF_F; l_i[i] = 0.f;
        #pragma unroll
        for (int j = 0; j < 4; j++) o[i][j] = 0.f;
    }

    for (int kt = 0; kt < SEQ; kt += 64) {
        __syncthreads();   // protect KPs/Vs from previous iteration's readers

        // K tile -> transposed [dim][key]
        #pragma unroll
        for (int t = 0; t < 4; t++) {
            int id = tid + t * 256;
            int r = id >> 4;          // key (local)
            int c = (id & 15) << 2;   // dim
            float4 v = *(const float4*)&Kg[(size_t)(kt + r) * DHEAD + c];
            KPs[c + 0][r] = v.x; KPs[c + 1][r] = v.y;
            KPs[c + 2][r] = v.z; KPs[c + 3][r] = v.w;
        }
        // V tile -> [key][dim]
        #pragma unroll
        for (int t = 0; t < 4; t++) {
            int id = tid + t * 256;
            int r = id >> 4, c = (id & 15) << 2;
            *(float4*)&Vs[r][c] =
                *(const float4*)&Vg[(size_t)(kt + r) * DHEAD + c];
        }
        __syncthreads();

        // S = Q @ K^T  (rows ty*4+i, cols tx*4+j)
        float s[4][4] = {};
        #pragma unroll 8
        for (int d = 0; d < 64; d++) {
            float a[4];
            #pragma unroll
            for (int i = 0; i < 4; i++) a[i] = Qs[ty * 4 + i][d];
            float4 b = *(float4*)&KPs[d][tx * 4];
            #pragma unroll
            for (int i = 0; i < 4; i++) {
                s[i][0] += a[i] * b.x; s[i][1] += a[i] * b.y;
                s[i][2] += a[i] * b.z; s[i][3] += a[i] * b.w;
            }
        }

        // online softmax (per-row state replicated across the 16 tx lanes)
        #pragma unroll
        for (int i = 0; i < 4; i++) {
            float rm = fmaxf(fmaxf(s[i][0], s[i][1]), fmaxf(s[i][2], s[i][3]));
            #pragma unroll
            for (int off = 8; off >= 1; off >>= 1)
                rm = fmaxf(rm, __shfl_xor_sync(0xffffffffu, rm, off));
            float mn = fmaxf(m_i[i], rm);
            float corr = __expf(m_i[i] - mn);
            m_i[i] = mn;
            float rs = 0.f;
            #pragma unroll
            for (int j = 0; j < 4; j++) {
                s[i][j] = __expf(s[i][j] - mn);
                rs += s[i][j];
            }
            #pragma unroll
            for (int off = 8; off >= 1; off >>= 1)
                rs += __shfl_xor_sync(0xffffffffu, rs, off);
            l_i[i] = l_i[i] * corr + rs;
            #pragma unroll
            for (int j = 0; j < 4; j++) o[i][j] *= corr;
        }

        __syncthreads();   // everyone done reading K before P overwrites it
        #pragma unroll
        for (int i = 0; i < 4; i++)
            *(float4*)&KPs[ty * 4 + i][tx * 4] =
                make_float4(s[i][0], s[i][1], s[i][2], s[i][3]);
        __syncthreads();

        // O += P @ V
        #pragma unroll 8
        for (int j = 0; j < 64; j++) {
            float a[4];
            #pragma unroll
            for (int i = 0; i < 4; i++) a[i] = KPs[ty * 4 + i][j];
            float4 b = *(float4*)&Vs[j][tx * 4];
            #pragma unroll
            for (int i = 0; i < 4; i++) {
                o[i][0] += a[i] * b.x; o[i][1] += a[i] * b.y;
                o[i][2] += a[i] * b.z; o[i][3] += a[i] * b.w;
            }
        }
    }

    // epilogue: O / l -> merged [B,N,H*DH]
    const int b = bh >> 3, h = bh & 7;
    #pragma unroll
    for (int i = 0; i < 4; i++) {
        float inv = 1.f / l_i[i];
        int q = q0 + ty * 4 + i;
        float4 v = make_float4(o[i][0] * inv, o[i][1] * inv,
                               o[i][2] * inv, o[i][3] * inv);
        *(float4*)&g_o[((size_t)(b * SEQ + q)) * DMODEL + h * DHEAD + tx * 4] = v;
    }
}

// ============================================================
// Kernel 3: out = AttnOut @ Wo + bo
// ============================================================
__global__ void __launch_bounds__(256) gemm_out(
    const float* __restrict__ Wo,
    const float* __restrict__ bo,
    float* __restrict__ out)
{
    __shared__ float As[64][33];
    __shared__ float Bs[32][68];

    const int tid = threadIdx.x;
    const int tx = tid & 15, ty = tid >> 4;
    const int m0 = blockIdx.x * 64, n0 = blockIdx.y * 64;

    float acc[4][4] = {};

    for (int k0 = 0; k0 < DMODEL; k0 += 32) {
        #pragma unroll
        for (int t = 0; t < 2; t++) {
            int id = tid + t * 256;
            int r = id >> 3, c = (id & 7) << 2;
            float4 v = *(const float4*)&g_o[(size_t)(m0 + r) * DMODEL + k0 + c];
            As[r][c + 0] = v.x; As[r][c + 1] = v.y;
            As[r][c + 2] = v.z; As[r][c + 3] = v.w;
        }
        #pragma unroll
        for (int t = 0; t < 2; t++) {
            int id = tid + t * 256;
            int r = id >> 4, c = (id & 15) << 2;
            *(float4*)&Bs[r][c] =
                *(const float4*)&Wo[(size_t)(k0 + r) * DMODEL + n0 + c];
        }
        __syncthreads();

        #pragma unroll 8
        for (int kk = 0; kk < 32; kk++) {
            float a[4];
            #pragma unroll
            for (int i = 0; i < 4; i++) a[i] = As[ty * 4 + i][kk];
            float4 b = *(float4*)&Bs[kk][tx * 4];
            #pragma unroll
            for (int i = 0; i < 4; i++) {
                acc[i][0] += a[i] * b.x; acc[i][1] += a[i] * b.y;
                acc[i][2] += a[i] * b.z; acc[i][3] += a[i] * b.w;
            }
        }
        __syncthreads();
    }

    const int nn = n0 + tx * 4;
    float4 bb = *(const float4*)&bo[nn];
    #pragma unroll
    for (int i = 0; i < 4; i++) {
        int m = m0 + ty * 4 + i;
        float4 v = make_float4(acc[i][0] + bb.x, acc[i][1] + bb.y,
                               acc[i][2] + bb.z, acc[i][3] + bb.w);
        *(float4*)&out[(size_t)m * DMODEL + nn] = v;
    }
}

// ============================================================
extern "C" void kernel_launch(void* const* d_in, const int* in_sizes, int n_in,
                              void* d_out, int out_size)
{
    const float* x  = (const float*)d_in[0];
    const float* Wq = (const float*)d_in[1];
    const float* Wk = (const float*)d_in[2];
    const float* Wv = (const float*)d_in[3];
    const float* Wo = (const float*)d_in[4];
    const float* bo = (const float*)d_in[5];
    float* out = (float*)d_out;

    const int attn_smem = 3 * 64 * 68 * (int)sizeof(float);  // 52224 B
    cudaFuncSetAttribute(attn_kernel,
                         cudaFuncAttributeMaxDynamicSharedMemorySize, attn_smem);

    gemm_qkv<<<dim3(MTOT / 64, DMODEL / 64, 3), 256>>>(x, Wq, Wk, Wv);
    attn_kernel<<<dim3(SEQ / 64, BATCH * NH), 256, attn_smem>>>();
    gemm_out<<<dim3(MTOT / 64, DMODEL / 64), 256>>>(Wo, bo, out);
}

// round 2
// speedup vs baseline: 2.0297x; 2.0297x over previous
#include <cuda_runtime.h>
#include <math_constants.h>

#define BATCH  2
#define SEQ    4096
#define DMODEL 512
#define NH     8
#define DHEAD  64
#define SCALE  0.125f            // 64^-0.5
#define MTOT   (BATCH*SEQ)       // 8192

// ---- scratch (device globals; no allocations allowed) ----
__device__ __align__(16) float g_q[BATCH*NH*SEQ*DHEAD];   // [B,H,N,DH]
__device__ __align__(16) float g_k[BATCH*NH*SEQ*DHEAD];
__device__ __align__(16) float g_v[BATCH*NH*SEQ*DHEAD];
__device__ __align__(16) float g_o[MTOT*DMODEL];          // [B,N,H*DH] merged

// ============================================================
// tf32 helpers
// ============================================================
__device__ __forceinline__ unsigned f2tf32(float x) {
    unsigned r;
    asm("cvt.rna.tf32.f32 %0, %1;" : "=r"(r) : "f"(x));
    return r;
}

__device__ __forceinline__ void mma_tf32(float c[4],
                                         unsigned a0, unsigned a1,
                                         unsigned a2, unsigned a3,
                                         unsigned b0, unsigned b1)
{
    asm volatile(
        "mma.sync.aligned.m16n8k8.row.col.f32.tf32.tf32.f32 "
        "{%0,%1,%2,%3}, {%4,%5,%6,%7}, {%8,%9}, {%0,%1,%2,%3};"
        : "+f"(c[0]), "+f"(c[1]), "+f"(c[2]), "+f"(c[3])
        : "r"(a0), "r"(a1), "r"(a2), "r"(a3), "r"(b0), "r"(b1));
}

// ============================================================
// Kernel 1: QKV projection (fp32 SIMT, unchanged)
// ============================================================
__global__ void __launch_bounds__(256) gemm_qkv(
    const float* __restrict__ X,
    const float* __restrict__ Wq,
    const float* __restrict__ Wk,
    const float* __restrict__ Wv)
{
    __shared__ float As[64][33];
    __shared__ float Bs[32][68];

    const float* W = (blockIdx.z == 0) ? Wq : (blockIdx.z == 1) ? Wk : Wv;
    float*       G = (blockIdx.z == 0) ? g_q : (blockIdx.z == 1) ? g_k : g_v;

    const int tid = threadIdx.x;
    const int tx = tid & 15, ty = tid >> 4;
    const int m0 = blockIdx.x * 64, n0 = blockIdx.y * 64;

    float acc[4][4] = {};

    for (int k0 = 0; k0 < DMODEL; k0 += 32) {
        #pragma unroll
        for (int t = 0; t < 2; t++) {
            int id = tid + t * 256;
            int r = id >> 3, c = (id & 7) << 2;
            float4 v = *(const float4*)&X[(size_t)(m0 + r) * DMODEL + k0 + c];
            As[r][c + 0] = v.x; As[r][c + 1] = v.y;
            As[r][c + 2] = v.z; As[r][c + 3] = v.w;
        }
        #pragma unroll
        for (int t = 0; t < 2; t++) {
            int id = tid + t * 256;
            int r = id >> 4, c = (id & 15) << 2;
            *(float4*)&Bs[r][c] =
                *(const float4*)&W[(size_t)(k0 + r) * DMODEL + n0 + c];
        }
        __syncthreads();

        #pragma unroll 8
        for (int kk = 0; kk < 32; kk++) {
            float a[4];
            #pragma unroll
            for (int i = 0; i < 4; i++) a[i] = As[ty * 4 + i][kk];
            float4 b = *(float4*)&Bs[kk][tx * 4];
            #pragma unroll
            for (int i = 0; i < 4; i++) {
                acc[i][0] += a[i] * b.x; acc[i][1] += a[i] * b.y;
                acc[i][2] += a[i] * b.z; acc[i][3] += a[i] * b.w;
            }
        }
        __syncthreads();
    }

    const int nn = n0 + tx * 4;
    const int h = nn >> 6, dd = nn & 63;
    #pragma unroll
    for (int i = 0; i < 4; i++) {
        int m = m0 + ty * 4 + i;
        int b = m >> 12, ns = m & 4095;
        float4 v = make_float4(acc[i][0], acc[i][1], acc[i][2], acc[i][3]);
        *(float4*)&G[(((size_t)(b * NH + h) * SEQ + ns) * DHEAD) + dd] = v;
    }
}

// ============================================================
// Kernel 2: flash attention, tf32 tensor cores.
// CTA = 256 thr (8 warps), Q tile 128 rows, KV tile 64.
// Warp w owns query rows [16w, 16w+16). mma m16n8k8 tf32.
// Smem: Qs[128][68] + Ks[64][68] + Vs[64][68] = 69632 B.
// ============================================================
#define QT   128
#define KT   64
#define QPAD 68

__global__ void __launch_bounds__(256) attn_kernel()
{
    extern __shared__ float sm[];
    float (*Qs)[QPAD] = (float(*)[QPAD])(sm);
    float (*Ks)[QPAD] = (float(*)[QPAD])(sm + QT * QPAD);
    float (*Vs)[QPAD] = (float(*)[QPAD])(sm + (QT + KT) * QPAD);

    const int tid  = threadIdx.x;
    const int lane = tid & 31;
    const int wp   = tid >> 5;        // 0..7
    const int tg   = lane & 3;        // thread-in-group (col group)
    const int gp   = lane >> 2;       // group id (row)
    const int bh   = blockIdx.y;
    const int q0   = blockIdx.x * QT;

    const float* Qg = g_q + (size_t)bh * SEQ * DHEAD;
    const float* Kg = g_k + (size_t)bh * SEQ * DHEAD;
    const float* Vg = g_v + (size_t)bh * SEQ * DHEAD;

    // ---- load Q tile (pre-scaled) into smem ----
    #pragma unroll
    for (int t = 0; t < 8; t++) {
        int id = tid + t * 256;           // 0..2047 float4s
        int r = id >> 4, c = (id & 15) << 2;
        float4 v = *(const float4*)&Qg[(size_t)(q0 + r) * DHEAD + c];
        v.x *= SCALE; v.y *= SCALE; v.z *= SCALE; v.w *= SCALE;
        *(float4*)&Qs[r][c] = v;
    }
    __syncthreads();

    // ---- Q fragments in registers (tf32), reused across all KV tiles ----
    unsigned qf[8][4];
    {
        const int qr = 16 * wp + gp;
        #pragma unroll
        for (int ks = 0; ks < 8; ks++) {
            qf[ks][0] = f2tf32(Qs[qr    ][8 * ks + tg    ]);
            qf[ks][1] = f2tf32(Qs[qr + 8][8 * ks + tg    ]);
            qf[ks][2] = f2tf32(Qs[qr    ][8 * ks + tg + 4]);
            qf[ks][3] = f2tf32(Qs[qr + 8][8 * ks + tg + 4]);
        }
    }

    float o[8][4];
    #pragma unroll
    for (int nt = 0; nt < 8; nt++)
        #pragma unroll
        for (int j = 0; j < 4; j++) o[nt][j] = 0.f;
    float m0r = -CUDART_INF_F, m1r = -CUDART_INF_F;
    float l0r = 0.f, l1r = 0.f;

    for (int kt = 0; kt < SEQ; kt += KT) {
        __syncthreads();   // previous tile's readers done

        // K, V tiles -> smem (tf32-rounded)
        #pragma unroll
        for (int t = 0; t < 4; t++) {
            int id = tid + t * 256;           // 0..1023 float4s
            int r = id >> 4, c = (id & 15) << 2;
            float4 v = *(const float4*)&Kg[(size_t)(kt + r) * DHEAD + c];
            Ks[r][c + 0] = __uint_as_float(f2tf32(v.x));
            Ks[r][c + 1] = __uint_as_float(f2tf32(v.y));
            Ks[r][c + 2] = __uint_as_float(f2tf32(v.z));
            Ks[r][c + 3] = __uint_as_float(f2tf32(v.w));
        }
        #pragma unroll
        for (int t = 0; t < 4; t++) {
            int id = tid + t * 256;
            int r = id >> 4, c = (id & 15) << 2;
            float4 v = *(const float4*)&Vg[(size_t)(kt + r) * DHEAD + c];
            Vs[r][c + 0] = __uint_as_float(f2tf32(v.x));
            Vs[r][c + 1] = __uint_as_float(f2tf32(v.y));
            Vs[r][c + 2] = __uint_as_float(f2tf32(v.z));
            Vs[r][c + 3] = __uint_as_float(f2tf32(v.w));
        }
        __syncthreads();

        // ---- S = Q @ K^T : 8 n-tiles x 8 k-steps of m16n8k8 ----
        float s[8][4];
        #pragma unroll
        for (int nt = 0; nt < 8; nt++)
            #pragma unroll
            for (int j = 0; j < 4; j++) s[nt][j] = 0.f;

        #pragma unroll
        for (int ks = 0; ks < 8; ks++) {
            #pragma unroll
            for (int nt = 0; nt < 8; nt++) {
                unsigned b0 = __float_as_uint(Ks[8 * nt + gp][8 * ks + tg    ]);
                unsigned b1 = __float_as_uint(Ks[8 * nt + gp][8 * ks + tg + 4]);
                mma_tf32(s[nt], qf[ks][0], qf[ks][1], qf[ks][2], qf[ks][3], b0, b1);
            }
        }

        // ---- online softmax on fragments ----
        float mx0 = -CUDART_INF_F, mx1 = -CUDART_INF_F;
        #pragma unroll
        for (int nt = 0; nt < 8; nt++) {
            mx0 = fmaxf(mx0, fmaxf(s[nt][0], s[nt][1]));
            mx1 = fmaxf(mx1, fmaxf(s[nt][2], s[nt][3]));
        }
        mx0 = fmaxf(mx0, __shfl_xor_sync(0xffffffffu, mx0, 1));
        mx0 = fmaxf(mx0, __shfl_xor_sync(0xffffffffu, mx0, 2));
        mx1 = fmaxf(mx1, __shfl_xor_sync(0xffffffffu, mx1, 1));
        mx1 = fmaxf(mx1, __shfl_xor_sync(0xffffffffu, mx1, 2));

        float mn0 = fmaxf(m0r, mx0), mn1 = fmaxf(m1r, mx1);
        float cr0 = __expf(m0r - mn0), cr1 = __expf(m1r - mn1);
        m0r = mn0; m1r = mn1;

        float sum0 = 0.f, sum1 = 0.f;
        #pragma unroll
        for (int nt = 0; nt < 8; nt++) {
            s[nt][0] = __expf(s[nt][0] - mn0); sum0 += s[nt][0];
            s[nt][1] = __expf(s[nt][1] - mn0); sum0 += s[nt][1];
            s[nt][2] = __expf(s[nt][2] - mn1); sum1 += s[nt][2];
            s[nt][3] = __expf(s[nt][3] - mn1); sum1 += s[nt][3];
        }
        sum0 += __shfl_xor_sync(0xffffffffu, sum0, 1);
        sum0 += __shfl_xor_sync(0xffffffffu, sum0, 2);
        sum1 += __shfl_xor_sync(0xffffffffu, sum1, 1);
        sum1 += __shfl_xor_sync(0xffffffffu, sum1, 2);
        l0r = l0r * cr0 + sum0;
        l1r = l1r * cr1 + sum1;

        #pragma unroll
        for (int nt = 0; nt < 8; nt++) {
            o[nt][0] *= cr0; o[nt][1] *= cr0;
            o[nt][2] *= cr1; o[nt][3] *= cr1;
        }

        // ---- O += P @ V : reshape P C-frags -> A-frags via shfl ----
        const int src0 = (lane & ~3) | (tg >> 1);
        const int src2 = src0 + 2;
        const bool odd = tg & 1;
        #pragma unroll
        for (int ks = 0; ks < 8; ks++) {
            float x00 = __shfl_sync(0xffffffffu, s[ks][0], src0);
            float x01 = __shfl_sync(0xffffffffu, s[ks][1], src0);
            float x10 = __shfl_sync(0xffffffffu, s[ks][2], src0);
            float x11 = __shfl_sync(0xffffffffu, s[ks][3], src0);
            float x20 = __shfl_sync(0xffffffffu, s[ks][0], src2);
            float x21 = __shfl_sync(0xffffffffu, s[ks][1], src2);
            float x30 = __shfl_sync(0xffffffffu, s[ks][2], src2);
            float x31 = __shfl_sync(0xffffffffu, s[ks][3], src2);
            unsigned a0 = f2tf32(odd ? x01 : x00);
            unsigned a1 = f2tf32(odd ? x11 : x10);
            unsigned a2 = f2tf32(odd ? x21 : x20);
            unsigned a3 = f2tf32(odd ? x31 : x30);
            #pragma unroll
            for (int nt = 0; nt < 8; nt++) {
                unsigned b0 = __float_as_uint(Vs[8 * ks + tg    ][8 * nt + gp]);
                unsigned b1 = __float_as_uint(Vs[8 * ks + tg + 4][8 * nt + gp]);
                mma_tf32(o[nt], a0, a1, a2, a3, b0, b1);
            }
        }
    }

    // ---- epilogue: O / l -> merged [B,N,H*DH] ----
    const int b = bh >> 3, h = bh & 7;
    const float inv0 = 1.f / l0r, inv1 = 1.f / l1r;
    const int qr0 = q0 + 16 * wp + gp;
    const int qr1 = qr0 + 8;
    #pragma unroll
    for (int nt = 0; nt < 8; nt++) {
        int col = h * DHEAD + 8 * nt + 2 * tg;
        *(float2*)&g_o[(size_t)(b * SEQ + qr0) * DMODEL + col] =
            make_float2(o[nt][0] * inv0, o[nt][1] * inv0);
        *(float2*)&g_o[(size_t)(b * SEQ + qr1) * DMODEL + col] =
            make_float2(o[nt][2] * inv1, o[nt][3] * inv1);
    }
}

// ============================================================
// Kernel 3: out = AttnOut @ Wo + bo (fp32 SIMT, unchanged)
// ============================================================
__global__ void __launch_bounds__(256) gemm_out(
    const float* __restrict__ Wo,
    const float* __restrict__ bo,
    float* __restrict__ out)
{
    __shared__ float As[64][33];
    __shared__ float Bs[32][68];

    const int tid = threadIdx.x;
    const int tx = tid & 15, ty = tid >> 4;
    const int m0 = blockIdx.x * 64, n0 = blockIdx.y * 64;

    float acc[4][4] = {};

    for (int k0 = 0; k0 < DMODEL; k0 += 32) {
        #pragma unroll
        for (int t = 0; t < 2; t++) {
            int id = tid + t * 256;
            int r = id >> 3, c = (id & 7) << 2;
            float4 v = *(const float4*)&g_o[(size_t)(m0 + r) * DMODEL + k0 + c];
            As[r][c + 0] = v.x; As[r][c + 1] = v.y;
            As[r][c + 2] = v.z; As[r][c + 3] = v.w;
        }
        #pragma unroll
        for (int t = 0; t < 2; t++) {
            int id = tid + t * 256;
            int r = id >> 4, c = (id & 15) << 2;
            *(float4*)&Bs[r][c] =
                *(const float4*)&Wo[(size_t)(k0 + r) * DMODEL + n0 + c];
        }
        __syncthreads();

        #pragma unroll 8
        for (int kk = 0; kk < 32; kk++) {
            float a[4];
            #pragma unroll
            for (int i = 0; i < 4; i++) a[i] = As[ty * 4 + i][kk];
            float4 b = *(float4*)&Bs[kk][tx * 4];
            #pragma unroll
            for (int i = 0; i < 4; i++) {
                acc[i][0] += a[i] * b.x; acc[i][1] += a[i] * b.y;
                acc[i][2] += a[i] * b.z; acc[i][3] += a[i] * b.w;
            }
        }
        __syncthreads();
    }

    const int nn = n0 + tx * 4;
    float4 bb = *(const float4*)&bo[nn];
    #pragma unroll
    for (int i = 0; i < 4; i++) {
        int m = m0 + ty * 4 + i;
        float4 v = make_float4(acc[i][0] + bb.x, acc[i][1] + bb.y,
                               acc[i][2] + bb.z, acc[i][3] + bb.w);
        *(float4*)&out[(size_t)m * DMODEL + nn] = v;
    }
}

// ============================================================
extern "C" void kernel_launch(void* const* d_in, const int* in_sizes, int n_in,
                              void* d_out, int out_size)
{
    const float* x  = (const float*)d_in[0];
    const float* Wq = (const float*)d_in[1];
    const float* Wk = (const float*)d_in[2];
    const float* Wv = (const float*)d_in[3];
    const float* Wo = (const float*)d_in[4];
    const float* bo = (const float*)d_in[5];
    float* out = (float*)d_out;

    const int attn_smem = (QT + 2 * KT) * QPAD * (int)sizeof(float); // 69632 B
    cudaFuncSetAttribute(attn_kernel,
                         cudaFuncAttributeMaxDynamicSharedMemorySize, attn_smem);

    gemm_qkv<<<dim3(MTOT / 64, DMODEL / 64, 3), 256>>>(x, Wq, Wk, Wv);
    attn_kernel<<<dim3(SEQ / QT, BATCH * NH), 256, attn_smem>>>();
    gemm_out<<<dim3(MTOT / 64, DMODEL / 64), 256>>>(Wo, bo, out);
}

// round 3
// speedup vs baseline: 2.7493x; 1.3546x over previous
#include <cuda_runtime.h>
#include <math_constants.h>

#define BATCH  2
#define SEQ    4096
#define DMODEL 512
#define NH     8
#define DHEAD  64
#define SCALE  0.125f            // 64^-0.5
#define MTOT   (BATCH*SEQ)       // 8192

// ---- scratch (device globals; no allocations allowed) ----
__device__ __align__(16) float g_q[BATCH*NH*SEQ*DHEAD];   // [B,H,N,DH]
__device__ __align__(16) float g_k[BATCH*NH*SEQ*DHEAD];
__device__ __align__(16) float g_v[BATCH*NH*SEQ*DHEAD];
__device__ __align__(16) float g_o[MTOT*DMODEL];          // [B,N,H*DH] merged

// ============================================================
// tf32 helpers
// ============================================================
__device__ __forceinline__ unsigned f2tf32(float x) {
    unsigned r;
    asm("cvt.rna.tf32.f32 %0, %1;" : "=r"(r) : "f"(x));
    return r;
}

__device__ __forceinline__ void mma_tf32(float c[4],
                                         unsigned a0, unsigned a1,
                                         unsigned a2, unsigned a3,
                                         unsigned b0, unsigned b1)
{
    asm volatile(
        "mma.sync.aligned.m16n8k8.row.col.f32.tf32.tf32.f32 "
        "{%0,%1,%2,%3}, {%4,%5,%6,%7}, {%8,%9}, {%0,%1,%2,%3};"
        : "+f"(c[0]), "+f"(c[1]), "+f"(c[2]), "+f"(c[3])
        : "r"(a0), "r"(a1), "r"(a2), "r"(a3), "r"(b0), "r"(b1));
}

// ============================================================
// Kernel 1: QKV projection, tf32 tensor cores.
// CTA: 256 thr (8 warps, 4x2), tile 128x128, BK=32.
// Warp tile 32x64 = 2 m-frags x 8 n-frags of m16n8k8.
// ============================================================
__global__ void __launch_bounds__(256) gemm_qkv(
    const float* __restrict__ X,
    const float* __restrict__ Wq,
    const float* __restrict__ Wk,
    const float* __restrict__ Wv)
{
    __shared__ float As[128][36];   // [m][k], tf32-rounded
    __shared__ float Bs[32][136];   // [k][n], tf32-rounded

    const float* W = (blockIdx.z == 0) ? Wq : (blockIdx.z == 1) ? Wk : Wv;
    float*       G = (blockIdx.z == 0) ? g_q : (blockIdx.z == 1) ? g_k : g_v;

    const int tid  = threadIdx.x;
    const int lane = tid & 31;
    const int wp   = tid >> 5;
    const int wm   = wp & 3;          // warp m: 0..3
    const int wn   = wp >> 2;         // warp n: 0..1
    const int tg   = lane & 3;
    const int gp   = lane >> 2;
    const int m0   = blockIdx.x * 128, n0 = blockIdx.y * 128;

    float c[2][8][4];
    #pragma unroll
    for (int mi = 0; mi < 2; mi++)
        #pragma unroll
        for (int ni = 0; ni < 8; ni++)
            #pragma unroll
            for (int j = 0; j < 4; j++) c[mi][ni][j] = 0.f;

    for (int k0 = 0; k0 < DMODEL; k0 += 32) {
        // A tile 128x32 (1024 float4s)
        #pragma unroll
        for (int t = 0; t < 4; t++) {
            int id = tid + t * 256;
            int r = id >> 3, cc = (id & 7) << 2;
            float4 v = *(const float4*)&X[(size_t)(m0 + r) * DMODEL + k0 + cc];
            As[r][cc + 0] = __uint_as_float(f2tf32(v.x));
            As[r][cc + 1] = __uint_as_float(f2tf32(v.y));
            As[r][cc + 2] = __uint_as_float(f2tf32(v.z));
            As[r][cc + 3] = __uint_as_float(f2tf32(v.w));
        }
        // B tile 32x128 (1024 float4s)
        #pragma unroll
        for (int t = 0; t < 4; t++) {
            int id = tid + t * 256;
            int r = id >> 5, cc = (id & 31) << 2;
            float4 v = *(const float4*)&W[(size_t)(k0 + r) * DMODEL + n0 + cc];
            Bs[r][cc + 0] = __uint_as_float(f2tf32(v.x));
            Bs[r][cc + 1] = __uint_as_float(f2tf32(v.y));
            Bs[r][cc + 2] = __uint_as_float(f2tf32(v.z));
            Bs[r][cc + 3] = __uint_as_float(f2tf32(v.w));
        }
        __syncthreads();

        #pragma unroll
        for (int ks = 0; ks < 4; ks++) {
            const int k = ks * 8;
            unsigned a[2][4];
            #pragma unroll
            for (int mi = 0; mi < 2; mi++) {
                int row = wm * 32 + mi * 16;
                a[mi][0] = __float_as_uint(As[row + gp    ][k + tg    ]);
                a[mi][1] = __float_as_uint(As[row + gp + 8][k + tg    ]);
                a[mi][2] = __float_as_uint(As[row + gp    ][k + tg + 4]);
                a[mi][3] = __float_as_uint(As[row + gp + 8][k + tg + 4]);
            }
            #pragma unroll
            for (int ni = 0; ni < 8; ni++) {
                int col = wn * 64 + ni * 8 + gp;
                unsigned b0 = __float_as_uint(Bs[k + tg    ][col]);
                unsigned b1 = __float_as_uint(Bs[k + tg + 4][col]);
                mma_tf32(c[0][ni], a[0][0], a[0][1], a[0][2], a[0][3], b0, b1);
                mma_tf32(c[1][ni], a[1][0], a[1][1], a[1][2], a[1][3], b0, b1);
            }
        }
        __syncthreads();
    }

    // scatter to [B,H,N,DH]
    #pragma unroll
    for (int mi = 0; mi < 2; mi++) {
        int r0 = m0 + wm * 32 + mi * 16 + gp;     // rows r0, r0+8
        #pragma unroll
        for (int ni = 0; ni < 8; ni++) {
            int nn = n0 + wn * 64 + ni * 8 + 2 * tg;
            int h = nn >> 6, dd = nn & 63;
            int b0i = r0 >> 12, ns0 = r0 & 4095;
            int r1 = r0 + 8;
            int b1i = r1 >> 12, ns1 = r1 & 4095;
            *(float2*)&G[(((size_t)(b0i * NH + h) * SEQ + ns0) * DHEAD) + dd] =
                make_float2(c[mi][ni][0], c[mi][ni][1]);
            *(float2*)&G[(((size_t)(b1i * NH + h) * SEQ + ns1) * DHEAD) + dd] =
                make_float2(c[mi][ni][2], c[mi][ni][3]);
        }
    }
}

// ============================================================
// Kernel 2: flash attention, tf32 tensor cores (unchanged from R2).
// ============================================================
#define QT   128
#define KT   64
#define QPAD 68

__global__ void __launch_bounds__(256) attn_kernel()
{
    extern __shared__ float sm[];
    float (*Qs)[QPAD] = (float(*)[QPAD])(sm);
    float (*Ks)[QPAD] = (float(*)[QPAD])(sm + QT * QPAD);
    float (*Vs)[QPAD] = (float(*)[QPAD])(sm + (QT + KT) * QPAD);

    const int tid  = threadIdx.x;
    const int lane = tid & 31;
    const int wp   = tid >> 5;
    const int tg   = lane & 3;
    const int gp   = lane >> 2;
    const int bh   = blockIdx.y;
    const int q0   = blockIdx.x * QT;

    const float* Qg = g_q + (size_t)bh * SEQ * DHEAD;
    const float* Kg = g_k + (size_t)bh * SEQ * DHEAD;
    const float* Vg = g_v + (size_t)bh * SEQ * DHEAD;

    #pragma unroll
    for (int t = 0; t < 8; t++) {
        int id = tid + t * 256;
        int r = id >> 4, c = (id & 15) << 2;
        float4 v = *(const float4*)&Qg[(size_t)(q0 + r) * DHEAD + c];
        v.x *= SCALE; v.y *= SCALE; v.z *= SCALE; v.w *= SCALE;
        *(float4*)&Qs[r][c] = v;
    }
    __syncthreads();

    unsigned qf[8][4];
    {
        const int qr = 16 * wp + gp;
        #pragma unroll
        for (int ks = 0; ks < 8; ks++) {
            qf[ks][0] = f2tf32(Qs[qr    ][8 * ks + tg    ]);
            qf[ks][1] = f2tf32(Qs[qr + 8][8 * ks + tg    ]);
            qf[ks][2] = f2tf32(Qs[qr    ][8 * ks + tg + 4]);
            qf[ks][3] = f2tf32(Qs[qr + 8][8 * ks + tg + 4]);
        }
    }

    float o[8][4];
    #pragma unroll
    for (int nt = 0; nt < 8; nt++)
        #pragma unroll
        for (int j = 0; j < 4; j++) o[nt][j] = 0.f;
    float m0r = -CUDART_INF_F, m1r = -CUDART_INF_F;
    float l0r = 0.f, l1r = 0.f;

    for (int kt = 0; kt < SEQ; kt += KT) {
        __syncthreads();

        #pragma unroll
        for (int t = 0; t < 4; t++) {
            int id = tid + t * 256;
            int r = id >> 4, c = (id & 15) << 2;
            float4 v = *(const float4*)&Kg[(size_t)(kt + r) * DHEAD + c];
            Ks[r][c + 0] = __uint_as_float(f2tf32(v.x));
            Ks[r][c + 1] = __uint_as_float(f2tf32(v.y));
            Ks[r][c + 2] = __uint_as_float(f2tf32(v.z));
            Ks[r][c + 3] = __uint_as_float(f2tf32(v.w));
        }
        #pragma unroll
        for (int t = 0; t < 4; t++) {
            int id = tid + t * 256;
            int r = id >> 4, c = (id & 15) << 2;
            float4 v = *(const float4*)&Vg[(size_t)(kt + r) * DHEAD + c];
            Vs[r][c + 0] = __uint_as_float(f2tf32(v.x));
            Vs[r][c + 1] = __uint_as_float(f2tf32(v.y));
            Vs[r][c + 2] = __uint_as_float(f2tf32(v.z));
            Vs[r][c + 3] = __uint_as_float(f2tf32(v.w));
        }
        __syncthreads();

        float s[8][4];
        #pragma unroll
        for (int nt = 0; nt < 8; nt++)
            #pragma unroll
            for (int j = 0; j < 4; j++) s[nt][j] = 0.f;

        #pragma unroll
        for (int ks = 0; ks < 8; ks++) {
            #pragma unroll
            for (int nt = 0; nt < 8; nt++) {
                unsigned b0 = __float_as_uint(Ks[8 * nt + gp][8 * ks + tg    ]);
                unsigned b1 = __float_as_uint(Ks[8 * nt + gp][8 * ks + tg + 4]);
                mma_tf32(s[nt], qf[ks][0], qf[ks][1], qf[ks][2], qf[ks][3], b0, b1);
            }
        }

        float mx0 = -CUDART_INF_F, mx1 = -CUDART_INF_F;
        #pragma unroll
        for (int nt = 0; nt < 8; nt++) {
            mx0 = fmaxf(mx0, fmaxf(s[nt][0], s[nt][1]));
            mx1 = fmaxf(mx1, fmaxf(s[nt][2], s[nt][3]));
        }
        mx0 = fmaxf(mx0, __shfl_xor_sync(0xffffffffu, mx0, 1));
        mx0 = fmaxf(mx0, __shfl_xor_sync(0xffffffffu, mx0, 2));
        mx1 = fmaxf(mx1, __shfl_xor_sync(0xffffffffu, mx1, 1));
        mx1 = fmaxf(mx1, __shfl_xor_sync(0xffffffffu, mx1, 2));

        float mn0 = fmaxf(m0r, mx0), mn1 = fmaxf(m1r, mx1);
        float cr0 = __expf(m0r - mn0), cr1 = __expf(m1r - mn1);
        m0r = mn0; m1r = mn1;

        float sum0 = 0.f, sum1 = 0.f;
        #pragma unroll
        for (int nt = 0; nt < 8; nt++) {
            s[nt][0] = __expf(s[nt][0] - mn0); sum0 += s[nt][0];
            s[nt][1] = __expf(s[nt][1] - mn0); sum0 += s[nt][1];
            s[nt][2] = __expf(s[nt][2] - mn1); sum1 += s[nt][2];
            s[nt][3] = __expf(s[nt][3] - mn1); sum1 += s[nt][3];
        }
        sum0 += __shfl_xor_sync(0xffffffffu, sum0, 1);
        sum0 += __shfl_xor_sync(0xffffffffu, sum0, 2);
        sum1 += __shfl_xor_sync(0xffffffffu, sum1, 1);
        sum1 += __shfl_xor_sync(0xffffffffu, sum1, 2);
        l0r = l0r * cr0 + sum0;
        l1r = l1r * cr1 + sum1;

        #pragma unroll
        for (int nt = 0; nt < 8; nt++) {
            o[nt][0] *= cr0; o[nt][1] *= cr0;
            o[nt][2] *= cr1; o[nt][3] *= cr1;
        }

        const int src0 = (lane & ~3) | (tg >> 1);
        const int src2 = src0 + 2;
        const bool odd = tg & 1;
        #pragma unroll
        for (int ks = 0; ks < 8; ks++) {
            float x00 = __shfl_sync(0xffffffffu, s[ks][0], src0);
            float x01 = __shfl_sync(0xffffffffu, s[ks][1], src0);
            float x10 = __shfl_sync(0xffffffffu, s[ks][2], src0);
            float x11 = __shfl_sync(0xffffffffu, s[ks][3], src0);
            float x20 = __shfl_sync(0xffffffffu, s[ks][0], src2);
            float x21 = __shfl_sync(0xffffffffu, s[ks][1], src2);
            float x30 = __shfl_sync(0xffffffffu, s[ks][2], src2);
            float x31 = __shfl_sync(0xffffffffu, s[ks][3], src2);
            unsigned a0 = f2tf32(odd ? x01 : x00);
            unsigned a1 = f2tf32(odd ? x11 : x10);
            unsigned a2 = f2tf32(odd ? x21 : x20);
            unsigned a3 = f2tf32(odd ? x31 : x30);
            #pragma unroll
            for (int nt = 0; nt < 8; nt++) {
                unsigned b0 = __float_as_uint(Vs[8 * ks + tg    ][8 * nt + gp]);
                unsigned b1 = __float_as_uint(Vs[8 * ks + tg + 4][8 * nt + gp]);
                mma_tf32(o[nt], a0, a1, a2, a3, b0, b1);
            }
        }
    }

    const int b = bh >> 3, h = bh & 7;
    const float inv0 = 1.f / l0r, inv1 = 1.f / l1r;
    const int qr0 = q0 + 16 * wp + gp;
    const int qr1 = qr0 + 8;
    #pragma unroll
    for (int nt = 0; nt < 8; nt++) {
        int col = h * DHEAD + 8 * nt + 2 * tg;
        *(float2*)&g_o[(size_t)(b * SEQ + qr0) * DMODEL + col] =
            make_float2(o[nt][0] * inv0, o[nt][1] * inv0);
        *(float2*)&g_o[(size_t)(b * SEQ + qr1) * DMODEL + col] =
            make_float2(o[nt][2] * inv1, o[nt][3] * inv1);
    }
}

// ============================================================
// Kernel 3: out = AttnOut @ Wo + bo, tf32 tensor cores.
// Same skeleton as gemm_qkv, direct [m][n] epilogue + bias.
// ============================================================
__global__ void __launch_bounds__(256) gemm_out(
    const float* __restrict__ Wo,
    const float* __restrict__ bo,
    float* __restrict__ out)
{
    __shared__ float As[128][36];
    __shared__ float Bs[32][136];

    const int tid  = threadIdx.x;
    const int lane = tid & 31;
    const int wp   = tid >> 5;
    const int wm   = wp & 3;
    const int wn   = wp >> 2;
    const int tg   = lane & 3;
    const int gp   = lane >> 2;
    const int m0   = blockIdx.x * 128, n0 = blockIdx.y * 128;

    float c[2][8][4];
    #pragma unroll
    for (int mi = 0; mi < 2; mi++)
        #pragma unroll
        for (int ni = 0; ni < 8; ni++)
            #pragma unroll
            for (int j = 0; j < 4; j++) c[mi][ni][j] = 0.f;

    for (int k0 = 0; k0 < DMODEL; k0 += 32) {
        #pragma unroll
        for (int t = 0; t < 4; t++) {
            int id = tid + t * 256;
            int r = id >> 3, cc = (id & 7) << 2;
            float4 v = *(const float4*)&g_o[(size_t)(m0 + r) * DMODEL + k0 + cc];
            As[r][cc + 0] = __uint_as_float(f2tf32(v.x));
            As[r][cc + 1] = __uint_as_float(f2tf32(v.y));
            As[r][cc + 2] = __uint_as_float(f2tf32(v.z));
            As[r][cc + 3] = __uint_as_float(f2tf32(v.w));
        }
        #pragma unroll
        for (int t = 0; t < 4; t++) {
            int id = tid + t * 256;
            int r = id >> 5, cc = (id & 31) << 2;
            float4 v = *(const float4*)&Wo[(size_t)(k0 + r) * DMODEL + n0 + cc];
            Bs[r][cc + 0] = __uint_as_float(f2tf32(v.x));
            Bs[r][cc + 1] = __uint_as_float(f2tf32(v.y));
            Bs[r][cc + 2] = __uint_as_float(f2tf32(v.z));
            Bs[r][cc + 3] = __uint_as_float(f2tf32(v.w));
        }
        __syncthreads();

        #pragma unroll
        for (int ks = 0; ks < 4; ks++) {
            const int k = ks * 8;
            unsigned a[2][4];
            #pragma unroll
            for (int mi = 0; mi < 2; mi++) {
                int row = wm * 32 + mi * 16;
                a[mi][0] = __float_as_uint(As[row + gp    ][k + tg    ]);
                a[mi][1] = __float_as_uint(As[row + gp + 8][k + tg    ]);
                a[mi][2] = __float_as_uint(As[row + gp    ][k + tg + 4]);
                a[mi][3] = __float_as_uint(As[row + gp + 8][k + tg + 4]);
            }
            #pragma unroll
            for (int ni = 0; ni < 8; ni++) {
                int col = wn * 64 + ni * 8 + gp;
                unsigned b0 = __float_as_uint(Bs[k + tg    ][col]);
                unsigned b1 = __float_as_uint(Bs[k + tg + 4][col]);
                mma_tf32(c[0][ni], a[0][0], a[0][1], a[0][2], a[0][3], b0, b1);
                mma_tf32(c[1][ni], a[1][0], a[1][1], a[1][2], a[1][3], b0, b1);
            }
        }
        __syncthreads();
    }

    #pragma unroll
    for (int mi = 0; mi < 2; mi++) {
        int r0 = m0 + wm * 32 + mi * 16 + gp;
        #pragma unroll
        for (int ni = 0; ni < 8; ni++) {
            int nn = n0 + wn * 64 + ni * 8 + 2 * tg;
            float2 bb = *(const float2*)&bo[nn];
            *(float2*)&out[(size_t)r0 * DMODEL + nn] =
                make_float2(c[mi][ni][0] + bb.x, c[mi][ni][1] + bb.y);
            *(float2*)&out[(size_t)(r0 + 8) * DMODEL + nn] =
                make_float2(c[mi][ni][2] + bb.x, c[mi][ni][3] + bb.y);
        }
    }
}

// ============================================================
extern "C" void kernel_launch(void* const* d_in, const int* in_sizes, int n_in,
                              void* d_out, int out_size)
{
    const float* x  = (const float*)d_in[0];
    const float* Wq = (const float*)d_in[1];
    const float* Wk = (const float*)d_in[2];
    const float* Wv = (const float*)d_in[3];
    const float* Wo = (const float*)d_in[4];
    const float* bo = (const float*)d_in[5];
    float* out = (float*)d_out;

    const int attn_smem = (QT + 2 * KT) * QPAD * (int)sizeof(float); // 69632 B
    cudaFuncSetAttribute(attn_kernel,
                         cudaFuncAttributeMaxDynamicSharedMemorySize, attn_smem);

    gemm_qkv<<<dim3(MTOT / 128, DMODEL / 128, 3), 256>>>(x, Wq, Wk, Wv);
    attn_kernel<<<dim3(SEQ / QT, BATCH * NH), 256, attn_smem>>>();
    gemm_out<<<dim3(MTOT / 128, DMODEL / 128), 256>>>(Wo, bo, out);
}

// round 4
// speedup vs baseline: 3.7353x; 1.3586x over previous
#include <cuda_runtime.h>
#include <math_constants.h>

#define BATCH  2
#define SEQ    4096
#define DMODEL 512
#define NH     8
#define DHEAD  64
#define SCALE  0.125f            // 64^-0.5
#define MTOT   (BATCH*SEQ)       // 8192

// ---- scratch (device globals; no allocations allowed) ----
// g_q, g_k: tf32-rounded, column-PERMUTED within each 8-dh group (q also pre-scaled)
// g_v: tf32-rounded, normal layout
__device__ __align__(16) float g_q[BATCH*NH*SEQ*DHEAD];   // [B,H,N,DH]
__device__ __align__(16) float g_k[BATCH*NH*SEQ*DHEAD];
__device__ __align__(16) float g_v[BATCH*NH*SEQ*DHEAD];
__device__ __align__(16) float g_o[MTOT*DMODEL];          // [B,N,H*DH] merged

// ============================================================
// helpers
// ============================================================
__device__ __forceinline__ unsigned f2tf32(float x) {
    unsigned r;
    asm("cvt.rna.tf32.f32 %0, %1;" : "=r"(r) : "f"(x));
    return r;
}

__device__ __forceinline__ void mma_tf32(float c[4],
                                         unsigned a0, unsigned a1,
                                         unsigned a2, unsigned a3,
                                         unsigned b0, unsigned b1)
{
    asm volatile(
        "mma.sync.aligned.m16n8k8.row.col.f32.tf32.tf32.f32 "
        "{%0,%1,%2,%3}, {%4,%5,%6,%7}, {%8,%9}, {%0,%1,%2,%3};"
        : "+f"(c[0]), "+f"(c[1]), "+f"(c[2]), "+f"(c[3])
        : "r"(a0), "r"(a1), "r"(a2), "r"(a3), "r"(b0), "r"(b1));
}

// column permutation within an 8-group: {c, c+4} -> {2c, 2c+1}
__device__ __forceinline__ int permc(int c) {
    int j = c & 7;
    int p = (j < 4) ? (2 * j) : (2 * (j - 4) + 1);
    return (c & ~7) | p;
}

__device__ __forceinline__ void cp16(float* dst_s, const float* src_g) {
    unsigned d = (unsigned)__cvta_generic_to_shared(dst_s);
    asm volatile("cp.async.cg.shared.global [%0], [%1], 16;" :: "r"(d), "l"(src_g));
}

// ============================================================
// Kernel 1: QKV projection, tf32 tensor cores.
// Epilogue: tf32-round; q,k permuted (+q prescaled); v normal.
// ============================================================
__global__ void __launch_bounds__(256) gemm_qkv(
    const float* __restrict__ X,
    const float* __restrict__ Wq,
    const float* __restrict__ Wk,
    const float* __restrict__ Wv)
{
    __shared__ float As[128][36];
    __shared__ float Bs[32][136];

    const int z = blockIdx.z;
    const float* W = (z == 0) ? Wq : (z == 1) ? Wk : Wv;
    float*       G = (z == 0) ? g_q : (z == 1) ? g_k : g_v;

    const int tid  = threadIdx.x;
    const int lane = tid & 31;
    const int wp   = tid >> 5;
    const int wm   = wp & 3;
    const int wn   = wp >> 2;
    const int tg   = lane & 3;
    const int gp   = lane >> 2;
    const int m0   = blockIdx.x * 128, n0 = blockIdx.y * 128;

    float c[2][8][4];
    #pragma unroll
    for (int mi = 0; mi < 2; mi++)
        #pragma unroll
        for (int ni = 0; ni < 8; ni++)
            #pragma unroll
            for (int j = 0; j < 4; j++) c[mi][ni][j] = 0.f;

    for (int k0 = 0; k0 < DMODEL; k0 += 32) {
        #pragma unroll
        for (int t = 0; t < 4; t++) {
            int id = tid + t * 256;
            int r = id >> 3, cc = (id & 7) << 2;
            float4 v = *(const float4*)&X[(size_t)(m0 + r) * DMODEL + k0 + cc];
            As[r][cc + 0] = __uint_as_float(f2tf32(v.x));
            As[r][cc + 1] = __uint_as_float(f2tf32(v.y));
            As[r][cc + 2] = __uint_as_float(f2tf32(v.z));
            As[r][cc + 3] = __uint_as_float(f2tf32(v.w));
        }
        #pragma unroll
        for (int t = 0; t < 4; t++) {
            int id = tid + t * 256;
            int r = id >> 5, cc = (id & 31) << 2;
            float4 v = *(const float4*)&W[(size_t)(k0 + r) * DMODEL + n0 + cc];
            Bs[r][cc + 0] = __uint_as_float(f2tf32(v.x));
            Bs[r][cc + 1] = __uint_as_float(f2tf32(v.y));
            Bs[r][cc + 2] = __uint_as_float(f2tf32(v.z));
            Bs[r][cc + 3] = __uint_as_float(f2tf32(v.w));
        }
        __syncthreads();

        #pragma unroll
        for (int ks = 0; ks < 4; ks++) {
            const int k = ks * 8;
            unsigned a[2][4];
            #pragma unroll
            for (int mi = 0; mi < 2; mi++) {
                int row = wm * 32 + mi * 16;
                a[mi][0] = __float_as_uint(As[row + gp    ][k + tg    ]);
                a[mi][1] = __float_as_uint(As[row + gp + 8][k + tg    ]);
                a[mi][2] = __float_as_uint(As[row + gp    ][k + tg + 4]);
                a[mi][3] = __float_as_uint(As[row + gp + 8][k + tg + 4]);
            }
            #pragma unroll
            for (int ni = 0; ni < 8; ni++) {
                int col = wn * 64 + ni * 8 + gp;
                unsigned b0 = __float_as_uint(Bs[k + tg    ][col]);
                unsigned b1 = __float_as_uint(Bs[k + tg + 4][col]);
                mma_tf32(c[0][ni], a[0][0], a[0][1], a[0][2], a[0][3], b0, b1);
                mma_tf32(c[1][ni], a[1][0], a[1][1], a[1][2], a[1][3], b0, b1);
            }
        }
        __syncthreads();
    }

    // epilogue: tf32-round; q/k permuted (+q prescaled); v normal [B,H,N,DH]
    #pragma unroll
    for (int mi = 0; mi < 2; mi++) {
        int r0 = m0 + wm * 32 + mi * 16 + gp;
        int r1 = r0 + 8;
        int b0i = r0 >> 12, ns0 = r0 & 4095;
        int b1i = r1 >> 12, ns1 = r1 & 4095;
        #pragma unroll
        for (int ni = 0; ni < 8; ni++) {
            int nn = n0 + wn * 64 + ni * 8 + 2 * tg;
            int h = nn >> 6, dd = nn & 63;
            float v0 = __uint_as_float(f2tf32(c[mi][ni][0]));
            float v1 = __uint_as_float(f2tf32(c[mi][ni][1]));
            float v2 = __uint_as_float(f2tf32(c[mi][ni][2]));
            float v3 = __uint_as_float(f2tf32(c[mi][ni][3]));
            size_t base0 = ((size_t)(b0i * NH + h) * SEQ + ns0) * DHEAD;
            size_t base1 = ((size_t)(b1i * NH + h) * SEQ + ns1) * DHEAD;
            if (z == 2) {
                *(float2*)&G[base0 + dd] = make_float2(v0, v1);
                *(float2*)&G[base1 + dd] = make_float2(v2, v3);
            } else {
                if (z == 0) { v0 *= SCALE; v1 *= SCALE; v2 *= SCALE; v3 *= SCALE; }
                int d0 = permc(dd), d1 = permc(dd + 1);
                G[base0 + d0] = v0; G[base0 + d1] = v1;
                G[base1 + d0] = v2; G[base1 + d1] = v3;
            }
        }
    }
}

// ============================================================
// Kernel 2: flash attention, tf32 mma, warp-M=32.
// CTA = 128 thr (4 warps) x 128 q-rows; KV tile 64, cp.async x2 buffers.
// Smem: 2 KV buffers (Ks 64x72 + Vs 64x72 each) + resident Qs 128x72.
// ============================================================
#define QT   128
#define KT   64
#define SKV  72
#define BUF_FLOATS (2*KT*SKV)          // 9216
#define NTILES (SEQ/KT)                // 64

__device__ __forceinline__ void issue_tile(float* sm, const float* Kg,
                                           const float* Vg, int kt, int buf, int tid)
{
    float* Ks = sm + buf * BUF_FLOATS;
    float* Vs = Ks + KT * SKV;
    #pragma unroll
    for (int t = 0; t < 8; t++) {
        int id = tid + t * 128;                 // 0..1023
        int r = id >> 4, c4 = (id & 15) << 2;   // 16B chunk
        cp16(&Ks[r * SKV + c4], &Kg[(size_t)(kt + r) * DHEAD + c4]);
    }
    #pragma unroll
    for (int t = 0; t < 8; t++) {
        int id = tid + t * 128;
        int r = id >> 4, c4 = (id & 15) << 2;
        cp16(&Vs[r * SKV + c4], &Vg[(size_t)(kt + r) * DHEAD + c4]);
    }
}

__global__ void __launch_bounds__(128, 2) attn_kernel()
{
    extern __shared__ float sm[];
    float* Qs = sm + 2 * BUF_FLOATS;   // 128 x 72, resident

    const int tid  = threadIdx.x;
    const int lane = tid & 31;
    const int wp   = tid >> 5;        // 0..3
    const int tg   = lane & 3;
    const int gp   = lane >> 2;
    const int bh   = blockIdx.y;
    const int q0   = blockIdx.x * QT;

    const float* Qg = g_q + (size_t)bh * SEQ * DHEAD;
    const float* Kg = g_k + (size_t)bh * SEQ * DHEAD;
    const float* Vg = g_v + (size_t)bh * SEQ * DHEAD;

    // stage Q (already rounded+scaled+permuted): straight copy
    #pragma unroll
    for (int t = 0; t < 16; t++) {
        int id = tid + t * 128;                 // 2048 float4s
        int r = id >> 4, c = (id & 15) << 2;
        *(float4*)&Qs[r * SKV + c] = *(const float4*)&Qg[(size_t)(q0 + r) * DHEAD + c];
    }

    float o[2][8][4];
    #pragma unroll
    for (int mi = 0; mi < 2; mi++)
        #pragma unroll
        for (int nt = 0; nt < 8; nt++)
            #pragma unroll
            for (int j = 0; j < 4; j++) o[mi][nt][j] = 0.f;
    float mrow[2][2], lrow[2][2];
    #pragma unroll
    for (int mi = 0; mi < 2; mi++) {
        mrow[mi][0] = mrow[mi][1] = -CUDART_INF_F;
        lrow[mi][0] = lrow[mi][1] = 0.f;
    }

    // prologue: prefetch tiles 0,1
    issue_tile(sm, Kg, Vg, 0, 0, tid);
    asm volatile("cp.async.commit_group;" ::: "memory");
    issue_tile(sm, Kg, Vg, KT, 1, tid);
    asm volatile("cp.async.commit_group;" ::: "memory");

    const int qrow0 = 32 * wp + gp;            // base q-row (mi=0)
    const int src0 = (lane & ~3) | (tg >> 1);
    const int src2 = src0 + 2;
    const bool odd = tg & 1;

    for (int t = 0; t < NTILES; t++) {
        asm volatile("cp.async.wait_group 1;" ::: "memory");
        __syncthreads();   // tile t visible to all; all warps done with t-1

        const float* Ks = sm + (t & 1) * BUF_FLOATS;
        const float* Vs = Ks + KT * SKV;

        // ---- S = Q @ K^T ----
        float s[2][8][4];
        #pragma unroll
        for (int mi = 0; mi < 2; mi++)
            #pragma unroll
            for (int nt = 0; nt < 8; nt++)
                #pragma unroll
                for (int j = 0; j < 4; j++) s[mi][nt][j] = 0.f;

        #pragma unroll
        for (int ks = 0; ks < 8; ks++) {
            unsigned a[2][4];
            #pragma unroll
            for (int mi = 0; mi < 2; mi++) {
                int qr = qrow0 + 16 * mi;
                float2 lo = *(const float2*)&Qs[qr * SKV + 8 * ks + 2 * tg];
                float2 hi = *(const float2*)&Qs[(qr + 8) * SKV + 8 * ks + 2 * tg];
                a[mi][0] = __float_as_uint(lo.x);
                a[mi][2] = __float_as_uint(lo.y);
                a[mi][1] = __float_as_uint(hi.x);
                a[mi][3] = __float_as_uint(hi.y);
            }
            #pragma unroll
            for (int nt = 0; nt < 8; nt++) {
                float2 kb = *(const float2*)&Ks[(8 * nt + gp) * SKV + 8 * ks + 2 * tg];
                unsigned b0 = __float_as_uint(kb.x);
                unsigned b1 = __float_as_uint(kb.y);
                mma_tf32(s[0][nt], a[0][0], a[0][1], a[0][2], a[0][3], b0, b1);
                mma_tf32(s[1][nt], a[1][0], a[1][1], a[1][2], a[1][3], b0, b1);
            }
        }

        // ---- online softmax (per m-frag) ----
        #pragma unroll
        for (int mi = 0; mi < 2; mi++) {
            float mx0 = -CUDART_INF_F, mx1 = -CUDART_INF_F;
            #pragma unroll
            for (int nt = 0; nt < 8; nt++) {
                mx0 = fmaxf(mx0, fmaxf(s[mi][nt][0], s[mi][nt][1]));
                mx1 = fmaxf(mx1, fmaxf(s[mi][nt][2], s[mi][nt][3]));
            }
            mx0 = fmaxf(mx0, __shfl_xor_sync(0xffffffffu, mx0, 1));
            mx0 = fmaxf(mx0, __shfl_xor_sync(0xffffffffu, mx0, 2));
            mx1 = fmaxf(mx1, __shfl_xor_sync(0xffffffffu, mx1, 1));
            mx1 = fmaxf(mx1, __shfl_xor_sync(0xffffffffu, mx1, 2));

            float mn0 = fmaxf(mrow[mi][0], mx0), mn1 = fmaxf(mrow[mi][1], mx1);
            float cr0 = __expf(mrow[mi][0] - mn0), cr1 = __expf(mrow[mi][1] - mn1);
            mrow[mi][0] = mn0; mrow[mi][1] = mn1;

            float sum0 = 0.f, sum1 = 0.f;
            #pragma unroll
            for (int nt = 0; nt < 8; nt++) {
                s[mi][nt][0] = __expf(s[mi][nt][0] - mn0); sum0 += s[mi][nt][0];
                s[mi][nt][1] = __expf(s[mi][nt][1] - mn0); sum0 += s[mi][nt][1];
                s[mi][nt][2] = __expf(s[mi][nt][2] - mn1); sum1 += s[mi][nt][2];
                s[mi][nt][3] = __expf(s[mi][nt][3] - mn1); sum1 += s[mi][nt][3];
            }
            sum0 += __shfl_xor_sync(0xffffffffu, sum0, 1);
            sum0 += __shfl_xor_sync(0xffffffffu, sum0, 2);
            sum1 += __shfl_xor_sync(0xffffffffu, sum1, 1);
            sum1 += __shfl_xor_sync(0xffffffffu, sum1, 2);
            lrow[mi][0] = lrow[mi][0] * cr0 + sum0;
            lrow[mi][1] = lrow[mi][1] * cr1 + sum1;

            #pragma unroll
            for (int nt = 0; nt < 8; nt++) {
                o[mi][nt][0] *= cr0; o[mi][nt][1] *= cr0;
                o[mi][nt][2] *= cr1; o[mi][nt][3] *= cr1;
            }
        }

        // ---- O += P @ V ----
        #pragma unroll
        for (int ks = 0; ks < 8; ks++) {
            unsigned a[2][4];
            #pragma unroll
            for (int mi = 0; mi < 2; mi++) {
                float x00 = __shfl_sync(0xffffffffu, s[mi][ks][0], src0);
                float x01 = __shfl_sync(0xffffffffu, s[mi][ks][1], src0);
                float x10 = __shfl_sync(0xffffffffu, s[mi][ks][2], src0);
                float x11 = __shfl_sync(0xffffffffu, s[mi][ks][3], src0);
                float x20 = __shfl_sync(0xffffffffu, s[mi][ks][0], src2);
                float x21 = __shfl_sync(0xffffffffu, s[mi][ks][1], src2);
                float x30 = __shfl_sync(0xffffffffu, s[mi][ks][2], src2);
                float x31 = __shfl_sync(0xffffffffu, s[mi][ks][3], src2);
                a[mi][0] = f2tf32(odd ? x01 : x00);
                a[mi][1] = f2tf32(odd ? x11 : x10);
                a[mi][2] = f2tf32(odd ? x21 : x20);
                a[mi][3] = f2tf32(odd ? x31 : x30);
            }
            #pragma unroll
            for (int nt = 0; nt < 8; nt++) {
                unsigned b0 = __float_as_uint(Vs[(8 * ks + tg    ) * SKV + 8 * nt + gp]);
                unsigned b1 = __float_as_uint(Vs[(8 * ks + tg + 4) * SKV + 8 * nt + gp]);
                mma_tf32(o[0][nt], a[0][0], a[0][1], a[0][2], a[0][3], b0, b1);
                mma_tf32(o[1][nt], a[1][0], a[1][1], a[1][2], a[1][3], b0, b1);
            }
        }

        __syncthreads();   // all done reading buf[t&1]
        if (t + 2 < NTILES)
            issue_tile(sm, Kg, Vg, (t + 2) * KT, t & 1, tid);
        asm volatile("cp.async.commit_group;" ::: "memory");   // may be empty
    }

    // ---- epilogue: O / l -> merged [B,N,H*DH] ----
    const int b = bh >> 3, h = bh & 7;
    #pragma unroll
    for (int mi = 0; mi < 2; mi++) {
        float inv0 = 1.f / lrow[mi][0], inv1 = 1.f / lrow[mi][1];
        int qr0 = q0 + 32 * wp + 16 * mi + gp;
        int qr1 = qr0 + 8;
        #pragma unroll
        for (int nt = 0; nt < 8; nt++) {
            int col = h * DHEAD + 8 * nt + 2 * tg;
            *(float2*)&g_o[(size_t)(b * SEQ + qr0) * DMODEL + col] =
                make_float2(o[mi][nt][0] * inv0, o[mi][nt][1] * inv0);
            *(float2*)&g_o[(size_t)(b * SEQ + qr1) * DMODEL + col] =
                make_float2(o[mi][nt][2] * inv1, o[mi][nt][3] * inv1);
        }
    }
}

// ============================================================
// Kernel 3: out = AttnOut @ Wo + bo, tf32 tensor cores.
// ============================================================
__global__ void __launch_bounds__(256) gemm_out(
    const float* __restrict__ Wo,
    const float* __restrict__ bo,
    float* __restrict__ out)
{
    __shared__ float As[128][36];
    __shared__ float Bs[32][136];

    const int tid  = threadIdx.x;
    const int lane = tid & 31;
    const int wp   = tid >> 5;
    const int wm   = wp & 3;
    const int wn   = wp >> 2;
    const int tg   = lane & 3;
    const int gp   = lane >> 2;
    const int m0   = blockIdx.x * 128, n0 = blockIdx.y * 128;

    float c[2][8][4];
    #pragma unroll
    for (int mi = 0; mi < 2; mi++)
        #pragma unroll
        for (int ni = 0; ni < 8; ni++)
            #pragma unroll
            for (int j = 0; j < 4; j++) c[mi][ni][j] = 0.f;

    for (int k0 = 0; k0 < DMODEL; k0 += 32) {
        #pragma unroll
        for (int t = 0; t < 4; t++) {
            int id = tid + t * 256;
            int r = id >> 3, cc = (id & 7) << 2;
            float4 v = *(const float4*)&g_o[(size_t)(m0 + r) * DMODEL + k0 + cc];
            As[r][cc + 0] = __uint_as_float(f2tf32(v.x));
            As[r][cc + 1] = __uint_as_float(f2tf32(v.y));
            As[r][cc + 2] = __uint_as_float(f2tf32(v.z));
            As[r][cc + 3] = __uint_as_float(f2tf32(v.w));
        }
        #pragma unroll
        for (int t = 0; t < 4; t++) {
            int id = tid + t * 256;
            int r = id >> 5, cc = (id & 31) << 2;
            float4 v = *(const float4*)&Wo[(size_t)(k0 + r) * DMODEL + n0 + cc];
            Bs[r][cc + 0] = __uint_as_float(f2tf32(v.x));
            Bs[r][cc + 1] = __uint_as_float(f2tf32(v.y));
            Bs[r][cc + 2] = __uint_as_float(f2tf32(v.z));
            Bs[r][cc + 3] = __uint_as_float(f2tf32(v.w));
        }
        __syncthreads();

        #pragma unroll
        for (int ks = 0; ks < 4; ks++) {
            const int k = ks * 8;
            unsigned a[2][4];
            #pragma unroll
            for (int mi = 0; mi < 2; mi++) {
                int row = wm * 32 + mi * 16;
                a[mi][0] = __float_as_uint(As[row + gp    ][k + tg    ]);
                a[mi][1] = __float_as_uint(As[row + gp + 8][k + tg    ]);
                a[mi][2] = __float_as_uint(As[row + gp    ][k + tg + 4]);
                a[mi][3] = __float_as_uint(As[row + gp + 8][k + tg + 4]);
            }
            #pragma unroll
            for (int ni = 0; ni < 8; ni++) {
                int col = wn * 64 + ni * 8 + gp;
                unsigned b0 = __float_as_uint(Bs[k + tg    ][col]);
                unsigned b1 = __float_as_uint(Bs[k + tg + 4][col]);
                mma_tf32(c[0][ni], a[0][0], a[0][1], a[0][2], a[0][3], b0, b1);
                mma_tf32(c[1][ni], a[1][0], a[1][1], a[1][2], a[1][3], b0, b1);
            }
        }
        __syncthreads();
    }

    #pragma unroll
    for (int mi = 0; mi < 2; mi++) {
        int r0 = m0 + wm * 32 + mi * 16 + gp;
        #pragma unroll
        for (int ni = 0; ni < 8; ni++) {
            int nn = n0 + wn * 64 + ni * 8 + 2 * tg;
            float2 bb = *(const float2*)&bo[nn];
            *(float2*)&out[(size_t)r0 * DMODEL + nn] =
                make_float2(c[mi][ni][0] + bb.x, c[mi][ni][1] + bb.y);
            *(float2*)&out[(size_t)(r0 + 8) * DMODEL + nn] =
                make_float2(c[mi][ni][2] + bb.x, c[mi][ni][3] + bb.y);
        }
    }
}

// ============================================================
extern "C" void kernel_launch(void* const* d_in, const int* in_sizes, int n_in,
                              void* d_out, int out_size)
{
    const float* x  = (const float*)d_in[0];
    const float* Wq = (const float*)d_in[1];
    const float* Wk = (const float*)d_in[2];
    const float* Wv = (const float*)d_in[3];
    const float* Wo = (const float*)d_in[4];
    const float* bo = (const float*)d_in[5];
    float* out = (float*)d_out;

    const int attn_smem = (2 * BUF_FLOATS + QT * SKV) * (int)sizeof(float); // 110592 B
    cudaFuncSetAttribute(attn_kernel,
                         cudaFuncAttributeMaxDynamicSharedMemorySize, attn_smem);

    gemm_qkv<<<dim3(MTOT / 128, DMODEL / 128, 3), 256>>>(x, Wq, Wk, Wv);
    attn_kernel<<<dim3(SEQ / QT, BATCH * NH), 128, attn_smem>>>();
    gemm_out<<<dim3(MTOT / 128, DMODEL / 128), 256>>>(Wo, bo, out);
}